// round 5
// baseline (speedup 1.0000x reference)
#include <cuda_runtime.h>

// Warp-per-sample 2-layer MLP, barrier-free, single-wave.
//   h = relu(x[b,:] @ w1[b,:,:] + b1[b,:])   (D=128 -> H=256)
//   out = h @ w2[b,:,:] + b2[b,:]            (H=256 -> C=64)
// B=4096, grid = 512 CTAs x 256 threads = 4096 warps = one warp per sample,
// exactly one wave across 148 SMs.
// GEMV1: lane t owns h columns {4t..4t+3, 128+4t..128+4t+3}; accumulates the
//        full D=128 in registers (256 float4 LDGs/lane) -> NO reduction.
// GEMV2: 128 float4 LDGs/lane + one shfl_xor(16).
// Only __syncwarp() between phases -- every warp streams loads continuously.

#define B_DIM 4096
#define D_DIM 128
#define H_DIM 256
#define C_DIM 64
#define NW 8            // warps (= samples) per CTA

__global__ void __launch_bounds__(256, 4) mlp_warp_kernel(
    const float* __restrict__ x,
    const float* __restrict__ w1,
    const float* __restrict__ b1,
    const float* __restrict__ w2,
    const float* __restrict__ b2,
    float* __restrict__ out)
{
    const int tid = threadIdx.x;
    const int w   = tid >> 5;        // warp id in CTA = sample slot
    const int t   = tid & 31;        // lane
    const int b   = blockIdx.x * NW + w;

    __shared__ float x_s[NW][D_DIM];   // 512 B / warp
    __shared__ float h_s[NW][H_DIM];   // 1 KB / warp

    // ---- stage x[b,:]: 32 lanes x float4 = 128 floats ----
    reinterpret_cast<float4*>(x_s[w])[t] =
        reinterpret_cast<const float4*>(x + (size_t)b * D_DIM)[t];
    __syncwarp();

    // ========== GEMV1: full-D register accumulation, no reduction ==========
    // w1[b] as float4[128][64]; lane t covers groups t and 32+t of each row.
    {
        const float4* w1v = reinterpret_cast<const float4*>(
            w1 + (size_t)b * D_DIM * H_DIM);

        float4 a0 = make_float4(0.f, 0.f, 0.f, 0.f);
        float4 a1 = make_float4(0.f, 0.f, 0.f, 0.f);
        #pragma unroll 8
        for (int d = 0; d < D_DIM; ++d) {
            const float  xv = x_s[w][d];
            const float4 wa = __ldcs(&w1v[d * (H_DIM / 4) + t]);
            const float4 wb = __ldcs(&w1v[d * (H_DIM / 4) + 32 + t]);
            a0.x = fmaf(xv, wa.x, a0.x);
            a0.y = fmaf(xv, wa.y, a0.y);
            a0.z = fmaf(xv, wa.z, a0.z);
            a0.w = fmaf(xv, wa.w, a0.w);
            a1.x = fmaf(xv, wb.x, a1.x);
            a1.y = fmaf(xv, wb.y, a1.y);
            a1.z = fmaf(xv, wb.z, a1.z);
            a1.w = fmaf(xv, wb.w, a1.w);
        }

        const float4* b1v = reinterpret_cast<const float4*>(b1 + (size_t)b * H_DIM);
        const float4 c0 = b1v[t];
        const float4 c1 = b1v[32 + t];
        float4 h0, h1;
        h0.x = fmaxf(a0.x + c0.x, 0.f);
        h0.y = fmaxf(a0.y + c0.y, 0.f);
        h0.z = fmaxf(a0.z + c0.z, 0.f);
        h0.w = fmaxf(a0.w + c0.w, 0.f);
        h1.x = fmaxf(a1.x + c1.x, 0.f);
        h1.y = fmaxf(a1.y + c1.y, 0.f);
        h1.z = fmaxf(a1.z + c1.z, 0.f);
        h1.w = fmaxf(a1.w + c1.w, 0.f);
        reinterpret_cast<float4*>(h_s[w])[t]      = h0;
        reinterpret_cast<float4*>(h_s[w])[32 + t] = h1;
    }
    __syncwarp();

    // ========== GEMV2: out[c] = sum_j h[j] * w2[j, c] ======================
    // w2[b] as float4[256][16]. Lane: (cg = t&15, jq = t>>4).
    // Lane covers rows j = 2i + jq -> half-warp reads one 256B row segment.
    {
        const float4* w2v = reinterpret_cast<const float4*>(
            w2 + (size_t)b * H_DIM * C_DIM);
        const int cg = t & 15;
        const int jq = t >> 4;

        float4 acc = make_float4(0.f, 0.f, 0.f, 0.f);
        #pragma unroll 8
        for (int i = 0; i < H_DIM / 2; ++i) {
            const int j = 2 * i + jq;
            const float  hv = h_s[w][j];
            const float4 wv = __ldcs(&w2v[j * (C_DIM / 4) + cg]);
            acc.x = fmaf(hv, wv.x, acc.x);
            acc.y = fmaf(hv, wv.y, acc.y);
            acc.z = fmaf(hv, wv.z, acc.z);
            acc.w = fmaf(hv, wv.w, acc.w);
        }

        // combine the two row-parity partials: lane t with lane t^16
        acc.x += __shfl_xor_sync(0xffffffff, acc.x, 16);
        acc.y += __shfl_xor_sync(0xffffffff, acc.y, 16);
        acc.z += __shfl_xor_sync(0xffffffff, acc.z, 16);
        acc.w += __shfl_xor_sync(0xffffffff, acc.w, 16);

        if (t < 16) {
            const float4 bb =
                reinterpret_cast<const float4*>(b2 + (size_t)b * C_DIM)[cg];
            acc.x += bb.x; acc.y += bb.y; acc.z += bb.z; acc.w += bb.w;
            __stcs(reinterpret_cast<float4*>(out + (size_t)b * C_DIM) + cg, acc);
        }
    }
}

extern "C" void kernel_launch(void* const* d_in, const int* in_sizes, int n_in,
                              void* d_out, int out_size)
{
    const float* x  = (const float*)d_in[0];
    const float* w1 = (const float*)d_in[1];
    const float* b1 = (const float*)d_in[2];
    const float* w2 = (const float*)d_in[3];
    const float* b2 = (const float*)d_in[4];
    float* out = (float*)d_out;

    mlp_warp_kernel<<<B_DIM / NW, 256>>>(x, w1, b1, w2, b2, out);
}

// round 6
// speedup vs baseline: 1.0371x; 1.0371x over previous
#include <cuda_runtime.h>

// Per-sample 2-layer MLP, ONE sample per 128-thread CTA (fine work quantum).
//   h = relu(x[b,:] @ w1[b,:,:] + b1[b,:])   (D=128 -> H=256)
//   out = h @ w2[b,:,:] + b2[b,:]            (H=256 -> C=64)
// B=4096, grid = 4096 CTAs x 128 threads.
// Inner loops identical to the best (R2/R4) kernel: GEMV1 64 float4
// LDGs/thread, GEMV2 32 float4 LDGs/thread. Smaller CTAs (192KB traffic
// each vs 384KB) shrink the end-of-kernel drain tail and smooth waves,
// while ~12 CTAs/SM keeps ~48 resident warps (same steady-state as R2).

#define B_DIM 4096
#define D_DIM 128
#define H_DIM 256
#define C_DIM 64

__global__ void __launch_bounds__(128, 12) mlp_1samp_kernel(
    const float* __restrict__ x,
    const float* __restrict__ w1,
    const float* __restrict__ b1,
    const float* __restrict__ w2,
    const float* __restrict__ b2,
    float* __restrict__ out)
{
    const int l = threadIdx.x;       // 0..127
    const int b = blockIdx.x;

    __shared__ float  x_s[D_DIM];
    __shared__ float  h_s[H_DIM];
    __shared__ float4 part[128];

    // ---- stage x[b,:] ----
    x_s[l] = x[(size_t)b * D_DIM + l];
    __syncthreads();

    // ================= GEMV1: h[j] = sum_d x[d] * w1[d, j] =================
    // w1[b] as float4[128][64]. Thread: (dchunk = l>>6 in 0..1, g = l&63).
    // 64 float4 loads per thread, warp-contiguous 1024B rows.
    {
        const float4* w1v = reinterpret_cast<const float4*>(
            w1 + (size_t)b * D_DIM * H_DIM);
        const int g     = l & 63;
        const int dbase = (l >> 6) * 64;

        float4 acc = make_float4(0.f, 0.f, 0.f, 0.f);
        #pragma unroll
        for (int i = 0; i < 64; ++i) {
            const int d = dbase + i;
            const float  xv = x_s[d];
            const float4 w  = __ldcs(&w1v[d * (H_DIM / 4) + g]);
            acc.x = fmaf(xv, w.x, acc.x);
            acc.y = fmaf(xv, w.y, acc.y);
            acc.z = fmaf(xv, w.z, acc.z);
            acc.w = fmaf(xv, w.w, acc.w);
        }
        part[l] = acc;
    }
    __syncthreads();

    // reduce 2 partials per column group, add bias, ReLU
    if (l < 64) {
        float4 s0 = part[l];
        float4 s1 = part[64 + l];
        float4 bb = reinterpret_cast<const float4*>(b1 + (size_t)b * H_DIM)[l];
        float4 h4;
        h4.x = fmaxf(s0.x + s1.x + bb.x, 0.f);
        h4.y = fmaxf(s0.y + s1.y + bb.y, 0.f);
        h4.z = fmaxf(s0.z + s1.z + bb.z, 0.f);
        h4.w = fmaxf(s0.w + s1.w + bb.w, 0.f);
        reinterpret_cast<float4*>(h_s)[l] = h4;
    }
    __syncthreads();

    // ================= GEMV2: out[c] = sum_j h[j] * w2[j, c] ===============
    // w2[b] as float4[256][16]. Thread: (jchunk = l>>4 in 0..7, cg = l&15).
    // 32 float4 loads per thread, coalesced 256B row segments.
    {
        const float4* w2v = reinterpret_cast<const float4*>(
            w2 + (size_t)b * H_DIM * C_DIM);
        const int cg    = l & 15;
        const int jbase = (l >> 4) * 32;

        float4 acc = make_float4(0.f, 0.f, 0.f, 0.f);
        #pragma unroll
        for (int i = 0; i < 32; ++i) {
            const int j = jbase + i;
            const float  hv = h_s[j];
            const float4 w  = __ldcs(&w2v[j * (C_DIM / 4) + cg]);
            acc.x = fmaf(hv, w.x, acc.x);
            acc.y = fmaf(hv, w.y, acc.y);
            acc.z = fmaf(hv, w.z, acc.z);
            acc.w = fmaf(hv, w.w, acc.w);
        }
        part[l] = acc;
    }
    __syncthreads();

    // reduce 8 partials per output group, add bias, streaming store
    if (l < 16) {
        float4 acc = part[l];
        #pragma unroll
        for (int k = 1; k < 8; ++k) {
            float4 p = part[k * 16 + l];
            acc.x += p.x; acc.y += p.y; acc.z += p.z; acc.w += p.w;
        }
        float4 bb = reinterpret_cast<const float4*>(b2 + (size_t)b * C_DIM)[l];
        acc.x += bb.x; acc.y += bb.y; acc.z += bb.z; acc.w += bb.w;
        __stcs(reinterpret_cast<float4*>(out + (size_t)b * C_DIM) + l, acc);
    }
}

extern "C" void kernel_launch(void* const* d_in, const int* in_sizes, int n_in,
                              void* d_out, int out_size)
{
    const float* x  = (const float*)d_in[0];
    const float* w1 = (const float*)d_in[1];
    const float* b1 = (const float*)d_in[2];
    const float* w2 = (const float*)d_in[3];
    const float* b2 = (const float*)d_in[4];
    float* out = (float*)d_out;

    mlp_1samp_kernel<<<B_DIM, 128>>>(x, w1, b1, w2, b2, out);
}

// round 7
// speedup vs baseline: 1.1635x; 1.1219x over previous
#include <cuda_runtime.h>

// Per-sample 2-layer MLP with ReLU-sparsity skipping in layer 2.
//   h = relu(x[b,:] @ w1[b,:,:] + b1[b,:])   (D=128 -> H=256)
//   out = h @ w2[b,:,:] + b2[b,:]            (H=256 -> C=64)
// Rows of w2 where h[j]==0 contribute exactly 0 and are NEVER LOADED.
// E[skip] = 50% of w2 (x,w1,b1 ~ N(0,1)) -> total HBM traffic 774MB -> ~646MB.
// Skeleton = R6 (proven 86% DRAM): 128 thr/CTA, 1 sample/CTA, grid 4096.

#define B_DIM 4096
#define D_DIM 128
#define H_DIM 256
#define C_DIM 64

__global__ void __launch_bounds__(128, 12) mlp_sparse_kernel(
    const float* __restrict__ x,
    const float* __restrict__ w1,
    const float* __restrict__ b1,
    const float* __restrict__ w2,
    const float* __restrict__ b2,
    float* __restrict__ out)
{
    const int l = threadIdx.x;       // 0..127
    const int b = blockIdx.x;

    __shared__ float  x_s[D_DIM];
    __shared__ float  h_s[H_DIM];
    __shared__ float4 part[128];
    __shared__ int    idx[H_DIM];    // compacted nonzero-h row indices
    __shared__ int    wcnt[8];
    __shared__ int    woff[8];
    __shared__ int    nnz_s;

    // ---- stage x[b,:] ----
    x_s[l] = x[(size_t)b * D_DIM + l];
    __syncthreads();

    // ================= GEMV1: h[j] = sum_d x[d] * w1[d, j] =================
    // w1[b] as float4[128][64]. Thread: (dchunk = l>>6, g = l&63).
    // 64 float4 loads/thread, warp-contiguous 1024B rows. (Unchanged: proven.)
    {
        const float4* w1v = reinterpret_cast<const float4*>(
            w1 + (size_t)b * D_DIM * H_DIM);
        const int g     = l & 63;
        const int dbase = (l >> 6) * 64;

        float4 acc = make_float4(0.f, 0.f, 0.f, 0.f);
        #pragma unroll
        for (int i = 0; i < 64; ++i) {
            const int d = dbase + i;
            const float  xv = x_s[d];
            const float4 w  = __ldcs(&w1v[d * (H_DIM / 4) + g]);
            acc.x = fmaf(xv, w.x, acc.x);
            acc.y = fmaf(xv, w.y, acc.y);
            acc.z = fmaf(xv, w.z, acc.z);
            acc.w = fmaf(xv, w.w, acc.w);
        }
        part[l] = acc;
    }
    __syncthreads();

    // reduce 2 partials, add bias, ReLU -> h_s
    if (l < 64) {
        float4 s0 = part[l];
        float4 s1 = part[64 + l];
        float4 bb = reinterpret_cast<const float4*>(b1 + (size_t)b * H_DIM)[l];
        float4 h4;
        h4.x = fmaxf(s0.x + s1.x + bb.x, 0.f);
        h4.y = fmaxf(s0.y + s1.y + bb.y, 0.f);
        h4.z = fmaxf(s0.z + s1.z + bb.z, 0.f);
        h4.w = fmaxf(s0.w + s1.w + bb.w, 0.f);
        reinterpret_cast<float4*>(h_s)[l] = h4;
    }
    __syncthreads();

    // ========== compact indices of nonzero h (ballot + 8-bucket scan) ======
    // Thread l covers j=l and j=l+128. 4 warps -> 8 ballot groups of 32 j's.
    const int wid  = l >> 5;
    const int lane = l & 31;
    const float h0 = h_s[l];
    const float h1 = h_s[128 + l];
    const unsigned m0 = __ballot_sync(0xffffffffu, h0 > 0.f);
    const unsigned m1 = __ballot_sync(0xffffffffu, h1 > 0.f);
    if (lane == 0) { wcnt[wid] = __popc(m0); wcnt[4 + wid] = __popc(m1); }
    __syncthreads();
    if (l == 0) {
        int s = 0;
        #pragma unroll
        for (int k = 0; k < 8; ++k) { woff[k] = s; s += wcnt[k]; }
        nnz_s = s;
    }
    __syncthreads();
    if (h0 > 0.f)
        idx[woff[wid]     + __popc(m0 & ((1u << lane) - 1u))] = l;
    if (h1 > 0.f)
        idx[woff[4 + wid] + __popc(m1 & ((1u << lane) - 1u))] = 128 + l;
    __syncthreads();
    const int nnz = nnz_s;

    // ========== GEMV2 (sparse): out[c] = sum_{j: h[j]>0} h[j] * w2[j, c] ===
    // w2[b] as float4[256][16]. Thread: (jslot = l>>4 in 0..7, cg = l&15).
    // Iterate only compacted rows; each row = contiguous 256B, coalesced.
    {
        const float4* w2v = reinterpret_cast<const float4*>(
            w2 + (size_t)b * H_DIM * C_DIM);
        const int cg    = l & 15;
        const int jslot = l >> 4;

        float4 acc = make_float4(0.f, 0.f, 0.f, 0.f);
        int i = jslot;
        // unrolled-by-2 main loop for load MLP
        for (; i + 8 < nnz; i += 16) {
            const int j0 = idx[i];
            const int j1 = idx[i + 8];
            const float  hv0 = h_s[j0];
            const float  hv1 = h_s[j1];
            const float4 w0  = __ldcs(&w2v[j0 * (C_DIM / 4) + cg]);
            const float4 wq  = __ldcs(&w2v[j1 * (C_DIM / 4) + cg]);
            acc.x = fmaf(hv0, w0.x, acc.x);
            acc.y = fmaf(hv0, w0.y, acc.y);
            acc.z = fmaf(hv0, w0.z, acc.z);
            acc.w = fmaf(hv0, w0.w, acc.w);
            acc.x = fmaf(hv1, wq.x, acc.x);
            acc.y = fmaf(hv1, wq.y, acc.y);
            acc.z = fmaf(hv1, wq.z, acc.z);
            acc.w = fmaf(hv1, wq.w, acc.w);
        }
        for (; i < nnz; i += 8) {
            const int j = idx[i];
            const float  hv = h_s[j];
            const float4 w  = __ldcs(&w2v[j * (C_DIM / 4) + cg]);
            acc.x = fmaf(hv, w.x, acc.x);
            acc.y = fmaf(hv, w.y, acc.y);
            acc.z = fmaf(hv, w.z, acc.z);
            acc.w = fmaf(hv, w.w, acc.w);
        }
        part[l] = acc;   // index = jslot*16 + cg
    }
    __syncthreads();

    // reduce 8 jslot-partials per cg, add bias, streaming store
    if (l < 16) {
        float4 acc = part[l];
        #pragma unroll
        for (int k = 1; k < 8; ++k) {
            float4 p = part[k * 16 + l];
            acc.x += p.x; acc.y += p.y; acc.z += p.z; acc.w += p.w;
        }
        float4 bb = reinterpret_cast<const float4*>(b2 + (size_t)b * C_DIM)[l];
        acc.x += bb.x; acc.y += bb.y; acc.z += bb.z; acc.w += bb.w;
        __stcs(reinterpret_cast<float4*>(out + (size_t)b * C_DIM) + l, acc);
    }
}

extern "C" void kernel_launch(void* const* d_in, const int* in_sizes, int n_in,
                              void* d_out, int out_size)
{
    const float* x  = (const float*)d_in[0];
    const float* w1 = (const float*)d_in[1];
    const float* b1 = (const float*)d_in[2];
    const float* w2 = (const float*)d_in[3];
    const float* b2 = (const float*)d_in[4];
    float* out = (float*)d_out;

    mlp_sparse_kernel<<<B_DIM, 128>>>(x, w1, b1, w2, b2, out);
}

// round 8
// speedup vs baseline: 1.1696x; 1.0052x over previous
#include <cuda_runtime.h>

// Per-sample 2-layer MLP with ReLU-sparsity skipping in layer 2,
// sparse GEMV2 software-pipelined for load MLP.
//   h = relu(x[b,:] @ w1[b,:,:] + b1[b,:])   (D=128 -> H=256)
//   out = h @ w2[b,:,:] + b2[b,:]            (H=256 -> C=64)
// Rows of w2 with h[j]==0 contribute exactly 0 and are never loaded
// (~50% of w2 skipped; total traffic ~646MB).
// R8 change: GEMV2 reads 4 idx entries up-front per iteration, then issues
// 4 independent LDGs -> restores per-thread in-flight loads that the
// LDS->LDG dependency chain was throttling in R7.

#define B_DIM 4096
#define D_DIM 128
#define H_DIM 256
#define C_DIM 64

__global__ void __launch_bounds__(128, 12) mlp_sparse2_kernel(
    const float* __restrict__ x,
    const float* __restrict__ w1,
    const float* __restrict__ b1,
    const float* __restrict__ w2,
    const float* __restrict__ b2,
    float* __restrict__ out)
{
    const int l = threadIdx.x;       // 0..127
    const int b = blockIdx.x;

    __shared__ float  x_s[D_DIM];
    __shared__ float  h_s[H_DIM];
    __shared__ float4 part[128];
    __shared__ int    idx[H_DIM];    // compacted nonzero-h row indices
    __shared__ int    wcnt[8];
    __shared__ int    woff[8];
    __shared__ int    nnz_s;

    // ---- stage x[b,:] ----
    x_s[l] = x[(size_t)b * D_DIM + l];
    __syncthreads();

    // ================= GEMV1: h[j] = sum_d x[d] * w1[d, j] =================
    // w1[b] as float4[128][64]. Thread: (dchunk = l>>6, g = l&63).
    // 64 float4 loads/thread, warp-contiguous 1024B rows. (Proven, unchanged.)
    {
        const float4* w1v = reinterpret_cast<const float4*>(
            w1 + (size_t)b * D_DIM * H_DIM);
        const int g     = l & 63;
        const int dbase = (l >> 6) * 64;

        float4 acc = make_float4(0.f, 0.f, 0.f, 0.f);
        #pragma unroll
        for (int i = 0; i < 64; ++i) {
            const int d = dbase + i;
            const float  xv = x_s[d];
            const float4 w  = __ldcs(&w1v[d * (H_DIM / 4) + g]);
            acc.x = fmaf(xv, w.x, acc.x);
            acc.y = fmaf(xv, w.y, acc.y);
            acc.z = fmaf(xv, w.z, acc.z);
            acc.w = fmaf(xv, w.w, acc.w);
        }
        part[l] = acc;
    }
    __syncthreads();

    // reduce 2 partials, add bias, ReLU -> h_s
    if (l < 64) {
        float4 s0 = part[l];
        float4 s1 = part[64 + l];
        float4 bb = reinterpret_cast<const float4*>(b1 + (size_t)b * H_DIM)[l];
        float4 h4;
        h4.x = fmaxf(s0.x + s1.x + bb.x, 0.f);
        h4.y = fmaxf(s0.y + s1.y + bb.y, 0.f);
        h4.z = fmaxf(s0.z + s1.z + bb.z, 0.f);
        h4.w = fmaxf(s0.w + s1.w + bb.w, 0.f);
        reinterpret_cast<float4*>(h_s)[l] = h4;
    }
    __syncthreads();

    // ========== compact indices of nonzero h (ballot + warp scan) ==========
    // Thread l covers j=l and j=l+128. 4 warps -> 8 ballot groups of 32 j's.
    const int wid  = l >> 5;
    const int lane = l & 31;
    const float h0 = h_s[l];
    const float h1 = h_s[128 + l];
    const unsigned m0 = __ballot_sync(0xffffffffu, h0 > 0.f);
    const unsigned m1 = __ballot_sync(0xffffffffu, h1 > 0.f);
    if (lane == 0) { wcnt[wid] = __popc(m0); wcnt[4 + wid] = __popc(m1); }
    __syncthreads();
    if (l < 32) {
        // warp 0: exclusive prefix over 8 counts via shfl scan
        int v = (l < 8) ? wcnt[l] : 0;
        int s = v;
        #pragma unroll
        for (int o = 1; o < 8; o <<= 1) {
            int u = __shfl_up_sync(0xffffffffu, s, o);
            if (l >= o) s += u;
        }
        if (l < 8) woff[l] = s - v;
        if (l == 7) nnz_s = s;
    }
    __syncthreads();
    if (h0 > 0.f)
        idx[woff[wid]     + __popc(m0 & ((1u << lane) - 1u))] = l;
    if (h1 > 0.f)
        idx[woff[4 + wid] + __popc(m1 & ((1u << lane) - 1u))] = 128 + l;
    __syncthreads();
    const int nnz = nnz_s;

    // ========== GEMV2 (sparse, pipelined): =================================
    // out[c] = sum_{j: h[j]>0} h[j] * w2[j, c]
    // w2[b] as float4[256][16]. Thread: (jslot = l>>4 in 0..7, cg = l&15).
    // 4 idx reads up-front per iteration -> 4 independent LDGs in flight.
    {
        const float4* w2v = reinterpret_cast<const float4*>(
            w2 + (size_t)b * H_DIM * C_DIM);
        const int cg    = l & 15;
        const int jslot = l >> 4;

        float4 acc = make_float4(0.f, 0.f, 0.f, 0.f);
        int i = jslot;
        for (; i + 24 < nnz; i += 32) {
            const int j0 = idx[i];
            const int j1 = idx[i + 8];
            const int j2 = idx[i + 16];
            const int j3 = idx[i + 24];
            const float4 wv0 = __ldcs(&w2v[j0 * (C_DIM / 4) + cg]);
            const float4 wv1 = __ldcs(&w2v[j1 * (C_DIM / 4) + cg]);
            const float4 wv2 = __ldcs(&w2v[j2 * (C_DIM / 4) + cg]);
            const float4 wv3 = __ldcs(&w2v[j3 * (C_DIM / 4) + cg]);
            const float hv0 = h_s[j0];
            const float hv1 = h_s[j1];
            const float hv2 = h_s[j2];
            const float hv3 = h_s[j3];
            acc.x = fmaf(hv0, wv0.x, acc.x);
            acc.y = fmaf(hv0, wv0.y, acc.y);
            acc.z = fmaf(hv0, wv0.z, acc.z);
            acc.w = fmaf(hv0, wv0.w, acc.w);
            acc.x = fmaf(hv1, wv1.x, acc.x);
            acc.y = fmaf(hv1, wv1.y, acc.y);
            acc.z = fmaf(hv1, wv1.z, acc.z);
            acc.w = fmaf(hv1, wv1.w, acc.w);
            acc.x = fmaf(hv2, wv2.x, acc.x);
            acc.y = fmaf(hv2, wv2.y, acc.y);
            acc.z = fmaf(hv2, wv2.z, acc.z);
            acc.w = fmaf(hv2, wv2.w, acc.w);
            acc.x = fmaf(hv3, wv3.x, acc.x);
            acc.y = fmaf(hv3, wv3.y, acc.y);
            acc.z = fmaf(hv3, wv3.z, acc.z);
            acc.w = fmaf(hv3, wv3.w, acc.w);
        }
        for (; i < nnz; i += 8) {
            const int j = idx[i];
            const float  hv = h_s[j];
            const float4 wv = __ldcs(&w2v[j * (C_DIM / 4) + cg]);
            acc.x = fmaf(hv, wv.x, acc.x);
            acc.y = fmaf(hv, wv.y, acc.y);
            acc.z = fmaf(hv, wv.z, acc.z);
            acc.w = fmaf(hv, wv.w, acc.w);
        }
        part[l] = acc;   // index = jslot*16 + cg
    }
    __syncthreads();

    // reduce 8 jslot-partials per cg, add bias, streaming store
    if (l < 16) {
        float4 acc = part[l];
        #pragma unroll
        for (int k = 1; k < 8; ++k) {
            float4 p = part[k * 16 + l];
            acc.x += p.x; acc.y += p.y; acc.z += p.z; acc.w += p.w;
        }
        float4 bb = reinterpret_cast<const float4*>(b2 + (size_t)b * C_DIM)[l];
        acc.x += bb.x; acc.y += bb.y; acc.z += bb.z; acc.w += bb.w;
        __stcs(reinterpret_cast<float4*>(out + (size_t)b * C_DIM) + l, acc);
    }
}

extern "C" void kernel_launch(void* const* d_in, const int* in_sizes, int n_in,
                              void* d_out, int out_size)
{
    const float* x  = (const float*)d_in[0];
    const float* w1 = (const float*)d_in[1];
    const float* b1 = (const float*)d_in[2];
    const float* w2 = (const float*)d_in[3];
    const float* b2 = (const float*)d_in[4];
    float* out = (float*)d_out;

    mlp_sparse2_kernel<<<B_DIM, 128>>>(x, w1, b1, w2, b2, out);
}

// round 9
// speedup vs baseline: 1.2060x; 1.0311x over previous
#include <cuda_runtime.h>

// Per-sample 2-layer MLP with ReLU-sparsity skipping in layer 2 via
// PREDICATED loads (no compaction, affine addresses).
//   h = relu(x[b,:] @ w1[b,:,:] + b1[b,:])   (D=128 -> H=256)
//   out = h @ w2[b,:,:] + b2[b,:]            (H=256 -> C=64)
// Rows of w2 with h[j]==0 contribute exactly 0 and are never loaded
// (~50% of w2 skipped, exact). h[j]>0 is uniform across each 16-lane group
// (all lanes of a group share j), so @P LDG skips with no divergence and
// the affine address lets ptxas front-batch loads like the dense loop --
// unlike R7/R8's LDS-dependent gather (sparse phase measured ~4.6 TB/s).

#define B_DIM 4096
#define D_DIM 128
#define H_DIM 256
#define C_DIM 64

__global__ void __launch_bounds__(128, 10) mlp_pred_kernel(
    const float* __restrict__ x,
    const float* __restrict__ w1,
    const float* __restrict__ b1,
    const float* __restrict__ w2,
    const float* __restrict__ b2,
    float* __restrict__ out)
{
    const int l = threadIdx.x;       // 0..127
    const int b = blockIdx.x;

    __shared__ float  x_s[D_DIM];
    __shared__ float  h_s[H_DIM];
    __shared__ float4 part[128];

    // ---- stage x[b,:] ----
    x_s[l] = x[(size_t)b * D_DIM + l];
    __syncthreads();

    // ================= GEMV1: h[j] = sum_d x[d] * w1[d, j] =================
    // w1[b] as float4[128][64]. Thread: (dchunk = l>>6, g = l&63).
    // 64 float4 loads/thread, warp-contiguous 1024B rows. (Proven, unchanged.)
    {
        const float4* w1v = reinterpret_cast<const float4*>(
            w1 + (size_t)b * D_DIM * H_DIM);
        const int g     = l & 63;
        const int dbase = (l >> 6) * 64;

        float4 acc = make_float4(0.f, 0.f, 0.f, 0.f);
        #pragma unroll
        for (int i = 0; i < 64; ++i) {
            const int d = dbase + i;
            const float  xv = x_s[d];
            const float4 w  = __ldcs(&w1v[d * (H_DIM / 4) + g]);
            acc.x = fmaf(xv, w.x, acc.x);
            acc.y = fmaf(xv, w.y, acc.y);
            acc.z = fmaf(xv, w.z, acc.z);
            acc.w = fmaf(xv, w.w, acc.w);
        }
        part[l] = acc;
    }
    __syncthreads();

    // reduce 2 partials, add bias, ReLU -> h_s
    if (l < 64) {
        float4 s0 = part[l];
        float4 s1 = part[64 + l];
        float4 bb = reinterpret_cast<const float4*>(b1 + (size_t)b * H_DIM)[l];
        float4 h4;
        h4.x = fmaxf(s0.x + s1.x + bb.x, 0.f);
        h4.y = fmaxf(s0.y + s1.y + bb.y, 0.f);
        h4.z = fmaxf(s0.z + s1.z + bb.z, 0.f);
        h4.w = fmaxf(s0.w + s1.w + bb.w, 0.f);
        reinterpret_cast<float4*>(h_s)[l] = h4;
    }
    __syncthreads();

    // ========== GEMV2 (sparse via predication): ============================
    // out[c] = sum_{j: h[j]>0} h[j] * w2[j, c]
    // w2[b] as float4[256][16]. Thread: (jslot = l>>4 in 0..7, cg = l&15).
    // Row j = jslot + 8*i (affine). h_s[j] uniform across the 16-lane group:
    // predicated-off LDG costs nothing, predicated-on loads batch freely.
    {
        const float4* w2v = reinterpret_cast<const float4*>(
            w2 + (size_t)b * H_DIM * C_DIM);
        const int cg    = l & 15;
        const int jslot = l >> 4;

        float4 acc = make_float4(0.f, 0.f, 0.f, 0.f);
        #pragma unroll 16
        for (int i = 0; i < H_DIM / 8; ++i) {
            const int j = jslot + i * 8;
            const float hv = h_s[j];
            if (hv > 0.f) {
                const float4 wv = __ldcs(&w2v[j * (C_DIM / 4) + cg]);
                acc.x = fmaf(hv, wv.x, acc.x);
                acc.y = fmaf(hv, wv.y, acc.y);
                acc.z = fmaf(hv, wv.z, acc.z);
                acc.w = fmaf(hv, wv.w, acc.w);
            }
        }
        part[l] = acc;   // index = jslot*16 + cg
    }
    __syncthreads();

    // reduce 8 jslot-partials per cg, add bias, streaming store
    if (l < 16) {
        float4 acc = part[l];
        #pragma unroll
        for (int k = 1; k < 8; ++k) {
            float4 p = part[k * 16 + l];
            acc.x += p.x; acc.y += p.y; acc.z += p.z; acc.w += p.w;
        }
        float4 bb = reinterpret_cast<const float4*>(b2 + (size_t)b * C_DIM)[l];
        acc.x += bb.x; acc.y += bb.y; acc.z += bb.z; acc.w += bb.w;
        __stcs(reinterpret_cast<float4*>(out + (size_t)b * C_DIM) + l, acc);
    }
}

extern "C" void kernel_launch(void* const* d_in, const int* in_sizes, int n_in,
                              void* d_out, int out_size)
{
    const float* x  = (const float*)d_in[0];
    const float* w1 = (const float*)d_in[1];
    const float* b1 = (const float*)d_in[2];
    const float* w2 = (const float*)d_in[3];
    const float* b2 = (const float*)d_in[4];
    float* out = (float*)d_out;

    mlp_pred_kernel<<<B_DIM, 128>>>(x, w1, b1, w2, b2, out);
}